// round 6
// baseline (speedup 1.0000x reference)
#include <cuda_runtime.h>
#include <math.h>

#define K_FR 8
#define B_SZ 8
#define CIN  512
#define COUT 256
#define H_   28
#define W_   28
#define HW   784
#define C4V  1024

// ---------------- scratch (device globals; no allocation at runtime) --------
__device__ float g_pf  [K_FR * B_SZ * COUT * HW];
__device__ float g_x   [B_SZ * COUT * HW];
__device__ float g_x2  [B_SZ * COUT * HW];
__device__ float g_o1  [B_SZ * COUT * HW];
__device__ float g_h   [B_SZ * C4V * HW];
__device__ float g_aS  [B_SZ * HW * HW];
__device__ float g_aC  [B_SZ * COUT * COUT];
__device__ float g_cat [B_SZ * 2 * COUT * HW];
__device__ float g_bnA [COUT];
__device__ float g_bnB [COUT];

// ---------------- 3xTF32 tensor-core GEMM, split-at-store ------------------
// 64x128 tile, 256 threads, __launch_bounds__(256,2) -> 2 CTAs/SM (72KB smem).
// smem value layout: float4 {hi(k), hi(k+4), lo(k), lo(k+4)}, row stride 48.
// TA: A stored [K,M]; else [M,K].  TB: B stored [N,K]; else [K,N].
// CONV: B tile materialized on the fly from x [C,H,W] (implicit im2col,
//       k -> (ci,t), n -> pixel; pad=1 3x3).
// epilogue: v = acc*scale[m]+bias[m]; relu; v = v*gamma + resid[m,n]
// Requires Kd % 16 == 0 (all call sites: 256/512/784/1024/2304).

__device__ __forceinline__ unsigned f2tf(float f) {
    unsigned u;
    asm("cvt.rna.tf32.f32 %0, %1;" : "=r"(u) : "f"(f));
    return u;
}
__device__ __forceinline__ void f2tf_split(float f, unsigned& hi, unsigned& lo) {
    hi = f2tf(f);
    lo = f2tf(f - __uint_as_float(hi));
}
__device__ __forceinline__ void mma_tf32(float4& d, const unsigned a[4], const unsigned b[2]) {
    asm volatile(
        "mma.sync.aligned.m16n8k8.row.col.f32.tf32.tf32.f32 "
        "{%0,%1,%2,%3}, {%4,%5,%6,%7}, {%8,%9}, {%0,%1,%2,%3};"
        : "+f"(d.x), "+f"(d.y), "+f"(d.z), "+f"(d.w)
        : "r"(a[0]), "r"(a[1]), "r"(a[2]), "r"(a[3]), "r"(b[0]), "r"(b[1]));
}

#define SSTR 48   // smem row stride in floats
#define BM 64
#define BN 128

template <bool TA, bool TB, int CONV>
__global__ void __launch_bounds__(256, 2) gemm_tc(
    const float* __restrict__ A, const float* __restrict__ Bm, float* __restrict__ C,
    int M, int N, int Kd, int lda, int ldb,
    long aS, int aDiv, long bS, long cS,
    const float* __restrict__ scaleC, const float* __restrict__ biasC, long biS,
    int relu, const float* __restrict__ gammaPtr,
    const float* __restrict__ resid, long rS)
{
    extern __shared__ float sm[];
    float* As = sm;                    // [2][BM][SSTR]
    float* Bs = sm + 2 * BM * SSTR;    // [2][BN][SSTR]

    const int z = blockIdx.z;
    A  += (long)(z / aDiv) * aS;
    Bm += (long)z * bS;
    C  += (long)z * cS;
    if (biasC) biasC += (long)(z / aDiv) * biS;
    if (resid) resid += (long)z * rS;

    const int tid  = threadIdx.x;
    const int lane = tid & 31, warp = tid >> 5;
    constexpr int MI = BM / 32, NJ = BN / 32;   // 2, 4
    constexpr int NA = BM * 16 / 256;           // 4
    constexpr int PA = NA / 2;                  // 2
    constexpr int NB = BN * 16 / 256;           // 8
    constexpr int PB = NB / 2;                  // 4
    const int wm = (warp >> 2) * (BM / 2);
    const int wn = (warp & 3) * (BN / 4);
    const int m0 = blockIdx.y * BM, n0 = blockIdx.x * BN;

    float4 acc[MI][NJ];
    #pragma unroll
    for (int i = 0; i < MI; ++i)
        #pragma unroll
        for (int j = 0; j < NJ; ++j)
            acc[i][j] = make_float4(0.f, 0.f, 0.f, 0.f);

    float va[NA], vb[NB];

    auto loadA = [&](int k0) {
        if (!TA) {
            #pragma unroll
            for (int t = 0; t < NA; ++t) {
                int i = tid + t * 256;
                int k = i & 15, m = i >> 4;
                int gm = m0 + m;
                va[t] = (gm < M) ? A[(long)gm * lda + k0 + k] : 0.f;
            }
        } else {
            int m = tid & (BM - 1), psel = tid >> 6;
            int gm = m0 + m;
            #pragma unroll
            for (int t = 0; t < PA; ++t) {
                int p = psel * PA + t;
                int kk = ((p >> 2) << 3) + (p & 3);
                va[2 * t]     = (gm < M) ? A[(long)(k0 + kk) * lda + gm] : 0.f;
                va[2 * t + 1] = (gm < M) ? A[(long)(k0 + kk + 4) * lda + gm] : 0.f;
            }
        }
    };
    auto loadB = [&](int k0) {
        if (CONV) {
            // implicit im2col: B[k,n] with k=(ci*9+t), n=pixel; pad=1 3x3
            #pragma unroll
            for (int t = 0; t < NB; ++t) {
                int i = tid + t * 256;
                int k = k0 + (i >> 7);
                int n = n0 + (i & 127);
                float v = 0.f;
                if (n < N) {
                    int ci = k / 9, tt = k - ci * 9;
                    int dh = tt / 3, dw = tt - dh * 3;
                    int hh = (n / W_) + dh - 1;
                    int ww = (n % W_) + dw - 1;
                    if (hh >= 0 && hh < H_ && ww >= 0 && ww < W_)
                        v = Bm[(long)ci * HW + hh * W_ + ww];
                }
                vb[t] = v;
            }
        } else if (TB) {
            #pragma unroll
            for (int t = 0; t < NB; ++t) {
                int i = tid + t * 256;
                int k = i & 15, n = i >> 4;
                int gn = n0 + n;
                vb[t] = (gn < N) ? Bm[(long)gn * ldb + k0 + k] : 0.f;
            }
        } else {
            int n = tid & (BN - 1), psel = tid >> 7;
            int gn = n0 + n;
            #pragma unroll
            for (int t = 0; t < PB; ++t) {
                int p = psel * PB + t;
                int kk = ((p >> 2) << 3) + (p & 3);
                vb[2 * t]     = (gn < N) ? Bm[(long)(k0 + kk) * ldb + gn] : 0.f;
                vb[2 * t + 1] = (gn < N) ? Bm[(long)(k0 + kk + 4) * ldb + gn] : 0.f;
            }
        }
    };
    auto storeA = [&](int buf) {
        if (!TA) {
            #pragma unroll
            for (int t = 0; t < NA; ++t) {
                int i = tid + t * 256;
                int k = i & 15, m = i >> 4;
                int g = k >> 3, kq = k & 3, half = (k >> 2) & 1;
                unsigned hi, lo;
                f2tf_split(va[t], hi, lo);
                float* base = &As[((long)(buf * BM + m)) * SSTR + g * 16 + kq * 4];
                base[half]     = __uint_as_float(hi);
                base[2 + half] = __uint_as_float(lo);
            }
        } else {
            int m = tid & (BM - 1), psel = tid >> 6;
            #pragma unroll
            for (int t = 0; t < PA; ++t) {
                int p = psel * PA + t;
                int g = p >> 2, kq = p & 3;
                unsigned h0, l0, h1, l1;
                f2tf_split(va[2 * t], h0, l0);
                f2tf_split(va[2 * t + 1], h1, l1);
                uint4 v = make_uint4(h0, h1, l0, l1);
                *(uint4*)&As[((long)(buf * BM + m)) * SSTR + g * 16 + kq * 4] = v;
            }
        }
    };
    auto storeB = [&](int buf) {
        if (CONV) {
            #pragma unroll
            for (int t = 0; t < NB; ++t) {
                int i = tid + t * 256;
                int k = i & 15 ? 0 : 0;  // placeholder (unused)
                (void)k;
                int kk = i >> 7;         // k within tile
                int n = i & 127;
                int g = kk >> 3, kq = kk & 3, half = (kk >> 2) & 1;
                unsigned hi, lo;
                f2tf_split(vb[t], hi, lo);
                float* base = &Bs[((long)(buf * BN + n)) * SSTR + g * 16 + kq * 4];
                base[half]     = __uint_as_float(hi);
                base[2 + half] = __uint_as_float(lo);
            }
        } else if (TB) {
            #pragma unroll
            for (int t = 0; t < NB; ++t) {
                int i = tid + t * 256;
                int k = i & 15, n = i >> 4;
                int g = k >> 3, kq = k & 3, half = (k >> 2) & 1;
                unsigned hi, lo;
                f2tf_split(vb[t], hi, lo);
                float* base = &Bs[((long)(buf * BN + n)) * SSTR + g * 16 + kq * 4];
                base[half]     = __uint_as_float(hi);
                base[2 + half] = __uint_as_float(lo);
            }
        } else {
            int n = tid & (BN - 1), psel = tid >> 7;
            #pragma unroll
            for (int t = 0; t < PB; ++t) {
                int p = psel * PB + t;
                int g = p >> 2, kq = p & 3;
                unsigned h0, l0, h1, l1;
                f2tf_split(vb[2 * t], h0, l0);
                f2tf_split(vb[2 * t + 1], h1, l1);
                uint4 v = make_uint4(h0, h1, l0, l1);
                *(uint4*)&Bs[((long)(buf * BN + n)) * SSTR + g * 16 + kq * 4] = v;
            }
        }
    };
    auto compute = [&](int buf) {
        #pragma unroll
        for (int g = 0; g < 2; ++g) {
            uint4 a0[MI], a1[MI], bv[NJ];
            #pragma unroll
            for (int i = 0; i < MI; ++i) {
                int r = wm + i * 16 + (lane >> 2);
                a0[i] = *(const uint4*)&As[((long)(buf * BM + r)) * SSTR + g * 16 + ((lane & 3) << 2)];
                a1[i] = *(const uint4*)&As[((long)(buf * BM + r + 8)) * SSTR + g * 16 + ((lane & 3) << 2)];
            }
            #pragma unroll
            for (int j = 0; j < NJ; ++j) {
                int c = wn + j * 8 + (lane >> 2);
                bv[j] = *(const uint4*)&Bs[((long)(buf * BN + c)) * SSTR + g * 16 + ((lane & 3) << 2)];
            }
            unsigned aH[MI][4], aL[MI][4], bH[NJ][2], bL[NJ][2];
            #pragma unroll
            for (int i = 0; i < MI; ++i) {
                aH[i][0] = a0[i].x; aH[i][1] = a1[i].x; aH[i][2] = a0[i].y; aH[i][3] = a1[i].y;
                aL[i][0] = a0[i].z; aL[i][1] = a1[i].z; aL[i][2] = a0[i].w; aL[i][3] = a1[i].w;
            }
            #pragma unroll
            for (int j = 0; j < NJ; ++j) {
                bH[j][0] = bv[j].x; bH[j][1] = bv[j].y;
                bL[j][0] = bv[j].z; bL[j][1] = bv[j].w;
            }
            #pragma unroll
            for (int j = 0; j < NJ; ++j)
                #pragma unroll
                for (int i = 0; i < MI; ++i)
                    mma_tf32(acc[i][j], aH[i], bH[j]);   // hi*hi
            #pragma unroll
            for (int j = 0; j < NJ; ++j)
                #pragma unroll
                for (int i = 0; i < MI; ++i)
                    mma_tf32(acc[i][j], aH[i], bL[j]);   // hi*lo
            #pragma unroll
            for (int j = 0; j < NJ; ++j)
                #pragma unroll
                for (int i = 0; i < MI; ++i)
                    mma_tf32(acc[i][j], aL[i], bH[j]);   // lo*hi
        }
    };

    int buf = 0;
    loadA(0); loadB(0);
    storeA(0); storeB(0);
    __syncthreads();

    for (int k0 = 0; k0 < Kd; k0 += 16) {
        bool more = (k0 + 16) < Kd;
        if (more) { loadA(k0 + 16); loadB(k0 + 16); }
        compute(buf);
        if (more) {
            storeA(buf ^ 1); storeB(buf ^ 1);
            __syncthreads();
            buf ^= 1;
        }
    }

    const float gmv = gammaPtr ? *gammaPtr : 1.f;
    #pragma unroll
    for (int i = 0; i < MI; ++i) {
        int r0 = m0 + wm + i * 16 + (lane >> 2);
        int r1 = r0 + 8;
        float sc0 = 1.f, bi0 = 0.f, sc1 = 1.f, bi1 = 0.f;
        if (scaleC) { if (r0 < M) sc0 = scaleC[r0]; if (r1 < M) sc1 = scaleC[r1]; }
        if (biasC)  { if (r0 < M) bi0 = biasC[r0];  if (r1 < M) bi1 = biasC[r1]; }
        #pragma unroll
        for (int j = 0; j < NJ; ++j) {
            int c = n0 + wn + j * 8 + ((lane & 3) << 1);
            float4 v = acc[i][j];
            if (r0 < M) {
                float x0 = v.x * sc0 + bi0, x1 = v.y * sc0 + bi0;
                if (relu) { x0 = fmaxf(x0, 0.f); x1 = fmaxf(x1, 0.f); }
                if (resid) {
                    if (c < N)     x0 = x0 * gmv + resid[(long)r0 * N + c];
                    if (c + 1 < N) x1 = x1 * gmv + resid[(long)r0 * N + c + 1];
                }
                if (c < N)     C[(long)r0 * N + c]     = x0;
                if (c + 1 < N) C[(long)r0 * N + c + 1] = x1;
            }
            if (r1 < M) {
                float y0 = v.z * sc1 + bi1, y1 = v.w * sc1 + bi1;
                if (relu) { y0 = fmaxf(y0, 0.f); y1 = fmaxf(y1, 0.f); }
                if (resid) {
                    if (c < N)     y0 = y0 * gmv + resid[(long)r1 * N + c];
                    if (c + 1 < N) y1 = y1 * gmv + resid[(long)r1 * N + c + 1];
                }
                if (c < N)     C[(long)r1 * N + c]     = y0;
                if (c + 1 < N) C[(long)r1 * N + c + 1] = y1;
            }
        }
    }
}

// ---------------- pointwise kernels -----------------------------------------
__global__ void tshuffle_kernel(const float* __restrict__ pf,
                                const float* __restrict__ gw,
                                const float* __restrict__ gb,
                                float* __restrict__ out)
{
    int idx = blockIdx.x * blockDim.x + threadIdx.x;
    if (idx >= B_SZ * COUT * HW) return;
    int c = (idx / HW) % COUT;
    float s = gb[c];
    #pragma unroll
    for (int k = 0; k < K_FR; ++k)
        s = fmaf(pf[(long)k * (B_SZ * COUT * HW) + idx], gw[c * K_FR + k], s);
    out[idx] = s;
}

__global__ void bnprep_kernel(const float* __restrict__ p,
                              float* __restrict__ a, float* __restrict__ b)
{
    int c = blockIdx.x * blockDim.x + threadIdx.x;
    if (c >= COUT) return;
    float g = p[c], be = p[COUT + c], m = p[2 * COUT + c], v = p[3 * COUT + c];
    float s = g * rsqrtf(v + 1e-5f);
    a[c] = s;
    b[c] = be - m * s;
}

__global__ void softmax_kernel(float* __restrict__ S, int len, float scale)
{
    float* p = S + (long)blockIdx.x * len;
    __shared__ float red[256];
    int tid = threadIdx.x;
    float mx = -1e30f;
    for (int j = tid; j < len; j += 256) mx = fmaxf(mx, p[j] * scale);
    red[tid] = mx; __syncthreads();
    for (int s = 128; s > 0; s >>= 1) {
        if (tid < s) red[tid] = fmaxf(red[tid], red[tid + s]);
        __syncthreads();
    }
    mx = red[0]; __syncthreads();
    float sum = 0.f;
    for (int j = tid; j < len; j += 256) {
        float e = expf(p[j] * scale - mx);
        p[j] = e; sum += e;
    }
    red[tid] = sum; __syncthreads();
    for (int s = 128; s > 0; s >>= 1) {
        if (tid < s) red[tid] += red[tid + s];
        __syncthreads();
    }
    float inv = 1.f / red[0];
    for (int j = tid; j < len; j += 256) p[j] *= inv;
}

__global__ void concat_kernel(const float* __restrict__ kf,
                              const float* __restrict__ x,
                              float* __restrict__ cat)
{
    long idx = (long)blockIdx.x * blockDim.x + threadIdx.x;
    const long total = (long)B_SZ * 2 * COUT * HW;
    if (idx >= total) return;
    int n = (int)(idx % HW);
    long r = idx / HW;
    int c = (int)(r % (2 * COUT));
    int b = (int)(r / (2 * COUT));
    cat[idx] = (c < COUT) ? kf[((long)b * COUT + c) * HW + n]
                          : x[((long)b * COUT + (c - COUT)) * HW + n];
}

// ---------------- host-side helpers -----------------------------------------
static const int SMB = (2 * BM + 2 * BN) * SSTR * 4;   // 72 KB

// mode: 0 = NN, 1 = TN (A transposed), 2 = NT (B transposed), 3 = CONV (NN + implicit im2col)
static void launch_gemm(int mode,
                        const float* A, const float* B, float* C,
                        int M, int N, int Kd, int lda, int ldb,
                        long aS, int aDiv, long bS, long cS,
                        const float* sc, const float* bi, long biS,
                        int relu, const float* gp,
                        const float* res, long rS, int Z)
{
    dim3 block(256);
    dim3 grid((N + BN - 1) / BN, (M + BM - 1) / BM, Z);
    switch (mode) {
    case 0:
        cudaFuncSetAttribute(gemm_tc<false,false,0>,
                             cudaFuncAttributeMaxDynamicSharedMemorySize, SMB);
        gemm_tc<false,false,0><<<grid, block, SMB>>>(A, B, C, M, N, Kd, lda, ldb,
            aS, aDiv, bS, cS, sc, bi, biS, relu, gp, res, rS);
        break;
    case 1:
        cudaFuncSetAttribute(gemm_tc<true,false,0>,
                             cudaFuncAttributeMaxDynamicSharedMemorySize, SMB);
        gemm_tc<true,false,0><<<grid, block, SMB>>>(A, B, C, M, N, Kd, lda, ldb,
            aS, aDiv, bS, cS, sc, bi, biS, relu, gp, res, rS);
        break;
    case 2:
        cudaFuncSetAttribute(gemm_tc<false,true,0>,
                             cudaFuncAttributeMaxDynamicSharedMemorySize, SMB);
        gemm_tc<false,true,0><<<grid, block, SMB>>>(A, B, C, M, N, Kd, lda, ldb,
            aS, aDiv, bS, cS, sc, bi, biS, relu, gp, res, rS);
        break;
    default:
        cudaFuncSetAttribute(gemm_tc<false,false,1>,
                             cudaFuncAttributeMaxDynamicSharedMemorySize, SMB);
        gemm_tc<false,false,1><<<grid, block, SMB>>>(A, B, C, M, N, Kd, lda, ldb,
            aS, aDiv, bS, cS, sc, bi, biS, relu, gp, res, rS);
        break;
    }
}

extern "C" void kernel_launch(void* const* d_in, const int* in_sizes, int n_in,
                              void* d_out, int out_size)
{
    const float* feats    = (const float*)d_in[0];
    const float* proj_w   = (const float*)d_in[1];
    const float* proj_b   = (const float*)d_in[2];
    const float* ts_gw    = (const float*)d_in[3];
    const float* ts_gb    = (const float*)d_in[4];
    const float* ts_w3    = (const float*)d_in[5];
    const float* ts_bn    = (const float*)d_in[6];
    const float* ssam_w1  = (const float*)d_in[7];
    const float* ssam_b1  = (const float*)d_in[8];
    const float* ssam_w2  = (const float*)d_in[9];
    const float* ssam_b2  = (const float*)d_in[10];
    const float* ssam_g   = (const float*)d_in[11];
    const float* csam_w1  = (const float*)d_in[12];
    const float* csam_b1  = (const float*)d_in[13];
    const float* csam_w2  = (const float*)d_in[14];
    const float* csam_b2  = (const float*)d_in[15];
    const float* fuse_w1  = (const float*)d_in[16];
    const float* fuse_bn1 = (const float*)d_in[17];
    const float* fuse_w2  = (const float*)d_in[18];
    const float* fuse_bn2 = (const float*)d_in[19];
    const float* fcsam_w1 = (const float*)d_in[20];
    const float* fcsam_b1 = (const float*)d_in[21];
    const float* fcsam_w2 = (const float*)d_in[22];
    const float* fcsam_b2 = (const float*)d_in[23];
    const float* fuse_w4  = (const float*)d_in[24];
    const float* fuse_bn4 = (const float*)d_in[25];
    float* out = (float*)d_out;

    float *pf, *x, *x2, *o1, *h, *aS_, *aC_, *cat, *bnA, *bnB;
    cudaGetSymbolAddress((void**)&pf,  g_pf);
    cudaGetSymbolAddress((void**)&x,   g_x);
    cudaGetSymbolAddress((void**)&x2,  g_x2);
    cudaGetSymbolAddress((void**)&o1,  g_o1);
    cudaGetSymbolAddress((void**)&h,   g_h);
    cudaGetSymbolAddress((void**)&aS_, g_aS);
    cudaGetSymbolAddress((void**)&aC_, g_aC);
    cudaGetSymbolAddress((void**)&cat, g_cat);
    cudaGetSymbolAddress((void**)&bnA, g_bnA);
    cudaGetSymbolAddress((void**)&bnB, g_bnB);

    const long SP  = (long)COUT * HW;
    const long SPH = (long)C4V * HW;
    const long SPS = (long)HW * HW;
    const long SPC = (long)COUT * COUT;
    const long SPCAT = (long)2 * COUT * HW;

    // 1. per-frame 1x1 projection
    launch_gemm(0, proj_w, feats, pf, COUT, HW, CIN, CIN, HW,
                (long)COUT * CIN, B_SZ, (long)CIN * HW, SP,
                nullptr, proj_b, COUT, 0, nullptr, nullptr, 0, K_FR * B_SZ);

    // 2. temporal shuffle + grouped 1x1 -> x
    {
        int total = B_SZ * COUT * HW;
        tshuffle_kernel<<<(total + 255) / 256, 256>>>(pf, ts_gw, ts_gb, x);
    }

    // 3. 3x3 conv (implicit im2col) + BN -> x2
    bnprep_kernel<<<1, 256>>>(ts_bn, bnA, bnB);
    launch_gemm(3, ts_w3, x, x2, COUT, HW, COUT * 9, COUT * 9, HW,
                0, 1, SP, SP, bnA, bnB, 0, 0, nullptr, nullptr, 0, B_SZ);

    // 4. spatial self-attention (input x2, output x)
    launch_gemm(1, x2, x2, aS_, HW, HW, COUT, HW, HW,
                SP, 1, SP, SPS, nullptr, nullptr, 0, 0, nullptr, nullptr, 0, B_SZ);
    softmax_kernel<<<B_SZ * HW, 256>>>(aS_, HW, 0.0625f);
    launch_gemm(2, x2, aS_, o1, COUT, HW, HW, HW, HW,
                SP, 1, SPS, SP, nullptr, nullptr, 0, 0, nullptr, nullptr, 0, B_SZ);
    launch_gemm(0, ssam_w1, o1, h, C4V, HW, COUT, COUT, HW,
                0, 1, SP, SPH, nullptr, ssam_b1, 0, 1, nullptr, nullptr, 0, B_SZ);
    launch_gemm(0, ssam_w2, h, x, COUT, HW, C4V, C4V, HW,
                0, 1, SPH, SP, nullptr, ssam_b2, 0, 0, ssam_g, x2, SP, B_SZ);

    // 5. channel self-attention (input x, output x2)
    launch_gemm(2, x, x, aC_, COUT, COUT, HW, HW, HW,
                SP, 1, SP, SPC, nullptr, nullptr, 0, 0, nullptr, nullptr, 0, B_SZ);
    softmax_kernel<<<B_SZ * COUT, 256>>>(aC_, COUT, 0.0625f);
    launch_gemm(0, aC_, x, o1, COUT, HW, COUT, COUT, HW,
                SPC, 1, SP, SP, nullptr, nullptr, 0, 0, nullptr, nullptr, 0, B_SZ);
    launch_gemm(0, csam_w1, o1, h, C4V, HW, COUT, COUT, HW,
                0, 1, SP, SPH, nullptr, csam_b1, 0, 1, nullptr, nullptr, 0, B_SZ);
    launch_gemm(0, csam_w2, h, x2, COUT, HW, C4V, C4V, HW,
                0, 1, SPH, SP, nullptr, csam_b2, 0, 0, nullptr, x, SP, B_SZ);

    // 6. fuse: concat keyframe feat (pf[K-1]) with x2
    {
        long total = (long)B_SZ * SPCAT;
        concat_kernel<<<(int)((total + 255) / 256), 256>>>(
            pf + (long)(K_FR - 1) * B_SZ * SP, x2, cat);
    }
    bnprep_kernel<<<1, 256>>>(fuse_bn1, bnA, bnB);
    launch_gemm(0, fuse_w1, cat, x, COUT, HW, 2 * COUT, 2 * COUT, HW,
                0, 1, SPCAT, SP, bnA, bnB, 0, 1, nullptr, nullptr, 0, B_SZ);

    // 7. 3x3 conv (implicit) + BN + relu -> x2
    bnprep_kernel<<<1, 256>>>(fuse_bn2, bnA, bnB);
    launch_gemm(3, fuse_w2, x, x2, COUT, HW, COUT * 9, COUT * 9, HW,
                0, 1, SP, SP, bnA, bnB, 0, 1, nullptr, nullptr, 0, B_SZ);

    // 8. channel self-attention (input x2, output x)
    launch_gemm(2, x2, x2, aC_, COUT, COUT, HW, HW, HW,
                SP, 1, SP, SPC, nullptr, nullptr, 0, 0, nullptr, nullptr, 0, B_SZ);
    softmax_kernel<<<B_SZ * COUT, 256>>>(aC_, COUT, 0.0625f);
    launch_gemm(0, aC_, x2, o1, COUT, HW, COUT, COUT, HW,
                SPC, 1, SP, SP, nullptr, nullptr, 0, 0, nullptr, nullptr, 0, B_SZ);
    launch_gemm(0, fcsam_w1, o1, h, C4V, HW, COUT, COUT, HW,
                0, 1, SP, SPH, nullptr, fcsam_b1, 0, 1, nullptr, nullptr, 0, B_SZ);
    launch_gemm(0, fcsam_w2, h, x, COUT, HW, C4V, C4V, HW,
                0, 1, SPH, SP, nullptr, fcsam_b2, 0, 0, nullptr, x2, SP, B_SZ);

    // 9. final 3x3 conv (implicit) + BN + relu -> d_out
    bnprep_kernel<<<1, 256>>>(fuse_bn4, bnA, bnB);
    launch_gemm(3, fuse_w4, x, out, COUT, HW, COUT * 9, COUT * 9, HW,
                0, 1, SP, SP, bnA, bnB, 0, 1, nullptr, nullptr, 0, B_SZ);
}

// round 7
// speedup vs baseline: 1.1696x; 1.1696x over previous
#include <cuda_runtime.h>
#include <math.h>

#define K_FR 8
#define B_SZ 8
#define CIN  512
#define COUT 256
#define H_   28
#define W_   28
#define HW   784
#define C4V  1024

// ---------------- scratch (device globals; no allocation at runtime) --------
__device__ float g_pf  [K_FR * B_SZ * COUT * HW];
__device__ float g_x   [B_SZ * COUT * HW];
__device__ float g_x2  [B_SZ * COUT * HW];
__device__ float g_o1  [B_SZ * COUT * HW];
__device__ float g_h   [B_SZ * C4V * HW];
__device__ float g_aS  [B_SZ * HW * HW];
__device__ float g_aC  [B_SZ * COUT * COUT];
__device__ float g_col [B_SZ * COUT * 9 * HW];
__device__ float g_cat [B_SZ * 2 * COUT * HW];
__device__ float g_bnA [COUT];
__device__ float g_bnB [COUT];

// ---------------- 3xTF32 tensor-core GEMM, split-at-store ------------------
// 64x128 tile, 256 threads, __launch_bounds__(256,2) -> 2 CTAs/SM (72KB smem).
// Mainloop: load(t+1) -> compute g0(t) -> split+STS(t+1) -> compute g1(t)
// so the staging tail overlaps half the HMMA work instead of serializing.
// smem value layout: float4 {hi(k), hi(k+4), lo(k), lo(k+4)}, row stride 48.
// TA: A stored [K,M]; else [M,K].  TB: B stored [N,K]; else [K,N].
// epilogue: v = acc*scale[m]+bias[m]; relu; v = v*gamma + resid[m,n]
// Requires Kd % 16 == 0 (all call sites: 256/512/784/1024/2304).

__device__ __forceinline__ unsigned f2tf(float f) {
    unsigned u;
    asm("cvt.rna.tf32.f32 %0, %1;" : "=r"(u) : "f"(f));
    return u;
}
__device__ __forceinline__ void f2tf_split(float f, unsigned& hi, unsigned& lo) {
    hi = f2tf(f);
    lo = f2tf(f - __uint_as_float(hi));
}
__device__ __forceinline__ void mma_tf32(float4& d, const unsigned a[4], const unsigned b[2]) {
    asm volatile(
        "mma.sync.aligned.m16n8k8.row.col.f32.tf32.tf32.f32 "
        "{%0,%1,%2,%3}, {%4,%5,%6,%7}, {%8,%9}, {%0,%1,%2,%3};"
        : "+f"(d.x), "+f"(d.y), "+f"(d.z), "+f"(d.w)
        : "r"(a[0]), "r"(a[1]), "r"(a[2]), "r"(a[3]), "r"(b[0]), "r"(b[1]));
}

#define SSTR 48   // smem row stride in floats
#define BM 64
#define BN 128

template <bool TA, bool TB>
__global__ void __launch_bounds__(256, 2) gemm_tc(
    const float* __restrict__ A, const float* __restrict__ Bm, float* __restrict__ C,
    int M, int N, int Kd, int lda, int ldb,
    long aS, int aDiv, long bS, long cS,
    const float* __restrict__ scaleC, const float* __restrict__ biasC, long biS,
    int relu, const float* __restrict__ gammaPtr,
    const float* __restrict__ resid, long rS)
{
    extern __shared__ float sm[];
    float* As = sm;                    // [2][BM][SSTR]
    float* Bs = sm + 2 * BM * SSTR;    // [2][BN][SSTR]

    const int z = blockIdx.z;
    A  += (long)(z / aDiv) * aS;
    Bm += (long)z * bS;
    C  += (long)z * cS;
    if (biasC) biasC += (long)(z / aDiv) * biS;
    if (resid) resid += (long)z * rS;

    const int tid  = threadIdx.x;
    const int lane = tid & 31, warp = tid >> 5;
    constexpr int MI = BM / 32, NJ = BN / 32;   // 2, 4
    constexpr int NA = BM * 16 / 256;           // 4
    constexpr int PA = NA / 2;                  // 2
    constexpr int NB = BN * 16 / 256;           // 8
    constexpr int PB = NB / 2;                  // 4
    const int wm = (warp >> 2) * (BM / 2);
    const int wn = (warp & 3) * (BN / 4);
    const int m0 = blockIdx.y * BM, n0 = blockIdx.x * BN;

    float4 acc[MI][NJ];
    #pragma unroll
    for (int i = 0; i < MI; ++i)
        #pragma unroll
        for (int j = 0; j < NJ; ++j)
            acc[i][j] = make_float4(0.f, 0.f, 0.f, 0.f);

    float va[NA], vb[NB];

    auto loadA = [&](int k0) {
        if (!TA) {
            #pragma unroll
            for (int t = 0; t < NA; ++t) {
                int i = tid + t * 256;
                int k = i & 15, m = i >> 4;
                int gm = m0 + m;
                va[t] = (gm < M) ? A[(long)gm * lda + k0 + k] : 0.f;
            }
        } else {
            int m = tid & (BM - 1), psel = tid >> 6;
            int gm = m0 + m;
            #pragma unroll
            for (int t = 0; t < PA; ++t) {
                int p = psel * PA + t;
                int kk = ((p >> 2) << 3) + (p & 3);
                va[2 * t]     = (gm < M) ? A[(long)(k0 + kk) * lda + gm] : 0.f;
                va[2 * t + 1] = (gm < M) ? A[(long)(k0 + kk + 4) * lda + gm] : 0.f;
            }
        }
    };
    auto loadB = [&](int k0) {
        if (TB) {
            #pragma unroll
            for (int t = 0; t < NB; ++t) {
                int i = tid + t * 256;
                int k = i & 15, n = i >> 4;
                int gn = n0 + n;
                vb[t] = (gn < N) ? Bm[(long)gn * ldb + k0 + k] : 0.f;
            }
        } else {
            int n = tid & (BN - 1), psel = tid >> 7;
            int gn = n0 + n;
            #pragma unroll
            for (int t = 0; t < PB; ++t) {
                int p = psel * PB + t;
                int kk = ((p >> 2) << 3) + (p & 3);
                vb[2 * t]     = (gn < N) ? Bm[(long)(k0 + kk) * ldb + gn] : 0.f;
                vb[2 * t + 1] = (gn < N) ? Bm[(long)(k0 + kk + 4) * ldb + gn] : 0.f;
            }
        }
    };
    auto storeA = [&](int buf) {
        if (!TA) {
            #pragma unroll
            for (int t = 0; t < NA; ++t) {
                int i = tid + t * 256;
                int k = i & 15, m = i >> 4;
                int g = k >> 3, kq = k & 3, half = (k >> 2) & 1;
                unsigned hi, lo;
                f2tf_split(va[t], hi, lo);
                float* base = &As[((long)(buf * BM + m)) * SSTR + g * 16 + kq * 4];
                base[half]     = __uint_as_float(hi);
                base[2 + half] = __uint_as_float(lo);
            }
        } else {
            int m = tid & (BM - 1), psel = tid >> 6;
            #pragma unroll
            for (int t = 0; t < PA; ++t) {
                int p = psel * PA + t;
                int g = p >> 2, kq = p & 3;
                unsigned h0, l0, h1, l1;
                f2tf_split(va[2 * t], h0, l0);
                f2tf_split(va[2 * t + 1], h1, l1);
                uint4 v = make_uint4(h0, h1, l0, l1);
                *(uint4*)&As[((long)(buf * BM + m)) * SSTR + g * 16 + kq * 4] = v;
            }
        }
    };
    auto storeB = [&](int buf) {
        if (TB) {
            #pragma unroll
            for (int t = 0; t < NB; ++t) {
                int i = tid + t * 256;
                int k = i & 15, n = i >> 4;
                int g = k >> 3, kq = k & 3, half = (k >> 2) & 1;
                unsigned hi, lo;
                f2tf_split(vb[t], hi, lo);
                float* base = &Bs[((long)(buf * BN + n)) * SSTR + g * 16 + kq * 4];
                base[half]     = __uint_as_float(hi);
                base[2 + half] = __uint_as_float(lo);
            }
        } else {
            int n = tid & (BN - 1), psel = tid >> 7;
            #pragma unroll
            for (int t = 0; t < PB; ++t) {
                int p = psel * PB + t;
                int g = p >> 2, kq = p & 3;
                unsigned h0, l0, h1, l1;
                f2tf_split(vb[2 * t], h0, l0);
                f2tf_split(vb[2 * t + 1], h1, l1);
                uint4 v = make_uint4(h0, h1, l0, l1);
                *(uint4*)&Bs[((long)(buf * BN + n)) * SSTR + g * 16 + kq * 4] = v;
            }
        }
    };
    // one K=8 half (g = 0 or 1) of a k-tile
    auto compute_g = [&](int buf, int g) {
        uint4 a0[MI], a1[MI], bv[NJ];
        #pragma unroll
        for (int i = 0; i < MI; ++i) {
            int r = wm + i * 16 + (lane >> 2);
            a0[i] = *(const uint4*)&As[((long)(buf * BM + r)) * SSTR + g * 16 + ((lane & 3) << 2)];
            a1[i] = *(const uint4*)&As[((long)(buf * BM + r + 8)) * SSTR + g * 16 + ((lane & 3) << 2)];
        }
        #pragma unroll
        for (int j = 0; j < NJ; ++j) {
            int c = wn + j * 8 + (lane >> 2);
            bv[j] = *(const uint4*)&Bs[((long)(buf * BN + c)) * SSTR + g * 16 + ((lane & 3) << 2)];
        }
        unsigned aH[MI][4], aL[MI][4], bH[NJ][2], bL[NJ][2];
        #pragma unroll
        for (int i = 0; i < MI; ++i) {
            aH[i][0] = a0[i].x; aH[i][1] = a1[i].x; aH[i][2] = a0[i].y; aH[i][3] = a1[i].y;
            aL[i][0] = a0[i].z; aL[i][1] = a1[i].z; aL[i][2] = a0[i].w; aL[i][3] = a1[i].w;
        }
        #pragma unroll
        for (int j = 0; j < NJ; ++j) {
            bH[j][0] = bv[j].x; bH[j][1] = bv[j].y;
            bL[j][0] = bv[j].z; bL[j][1] = bv[j].w;
        }
        #pragma unroll
        for (int j = 0; j < NJ; ++j)
            #pragma unroll
            for (int i = 0; i < MI; ++i)
                mma_tf32(acc[i][j], aH[i], bH[j]);   // hi*hi
        #pragma unroll
        for (int j = 0; j < NJ; ++j)
            #pragma unroll
            for (int i = 0; i < MI; ++i)
                mma_tf32(acc[i][j], aH[i], bL[j]);   // hi*lo
        #pragma unroll
        for (int j = 0; j < NJ; ++j)
            #pragma unroll
            for (int i = 0; i < MI; ++i)
                mma_tf32(acc[i][j], aL[i], bH[j]);   // lo*hi
    };

    int buf = 0;
    loadA(0); loadB(0);
    storeA(0); storeB(0);
    __syncthreads();

    for (int k0 = 0; k0 < Kd; k0 += 16) {
        bool more = (k0 + 16) < Kd;
        if (more) { loadA(k0 + 16); loadB(k0 + 16); }
        compute_g(buf, 0);
        if (more) { storeA(buf ^ 1); storeB(buf ^ 1); }   // overlaps with g=1 HMMAs
        compute_g(buf, 1);
        if (more) {
            __syncthreads();
            buf ^= 1;
        }
    }

    const float gmv = gammaPtr ? *gammaPtr : 1.f;
    #pragma unroll
    for (int i = 0; i < MI; ++i) {
        int r0 = m0 + wm + i * 16 + (lane >> 2);
        int r1 = r0 + 8;
        float sc0 = 1.f, bi0 = 0.f, sc1 = 1.f, bi1 = 0.f;
        if (scaleC) { if (r0 < M) sc0 = scaleC[r0]; if (r1 < M) sc1 = scaleC[r1]; }
        if (biasC)  { if (r0 < M) bi0 = biasC[r0];  if (r1 < M) bi1 = biasC[r1]; }
        #pragma unroll
        for (int j = 0; j < NJ; ++j) {
            int c = n0 + wn + j * 8 + ((lane & 3) << 1);
            float4 v = acc[i][j];
            if (r0 < M) {
                float x0 = v.x * sc0 + bi0, x1 = v.y * sc0 + bi0;
                if (relu) { x0 = fmaxf(x0, 0.f); x1 = fmaxf(x1, 0.f); }
                if (resid) {
                    if (c < N)     x0 = x0 * gmv + resid[(long)r0 * N + c];
                    if (c + 1 < N) x1 = x1 * gmv + resid[(long)r0 * N + c + 1];
                }
                if (c < N)     C[(long)r0 * N + c]     = x0;
                if (c + 1 < N) C[(long)r0 * N + c + 1] = x1;
            }
            if (r1 < M) {
                float y0 = v.z * sc1 + bi1, y1 = v.w * sc1 + bi1;
                if (relu) { y0 = fmaxf(y0, 0.f); y1 = fmaxf(y1, 0.f); }
                if (resid) {
                    if (c < N)     y0 = y0 * gmv + resid[(long)r1 * N + c];
                    if (c + 1 < N) y1 = y1 * gmv + resid[(long)r1 * N + c + 1];
                }
                if (c < N)     C[(long)r1 * N + c]     = y0;
                if (c + 1 < N) C[(long)r1 * N + c + 1] = y1;
            }
        }
    }
}

// ---------------- pointwise kernels -----------------------------------------
__global__ void tshuffle_kernel(const float* __restrict__ pf,
                                const float* __restrict__ gw,
                                const float* __restrict__ gb,
                                float* __restrict__ out)
{
    int idx = blockIdx.x * blockDim.x + threadIdx.x;
    if (idx >= B_SZ * COUT * HW) return;
    int c = (idx / HW) % COUT;
    float s = gb[c];
    #pragma unroll
    for (int k = 0; k < K_FR; ++k)
        s = fmaf(pf[(long)k * (B_SZ * COUT * HW) + idx], gw[c * K_FR + k], s);
    out[idx] = s;
}

__global__ void bnprep_kernel(const float* __restrict__ p,
                              float* __restrict__ a, float* __restrict__ b)
{
    int c = blockIdx.x * blockDim.x + threadIdx.x;
    if (c >= COUT) return;
    float g = p[c], be = p[COUT + c], m = p[2 * COUT + c], v = p[3 * COUT + c];
    float s = g * rsqrtf(v + 1e-5f);
    a[c] = s;
    b[c] = be - m * s;
}

__global__ void im2col_kernel(const float* __restrict__ x, float* __restrict__ col)
{
    long idx = (long)blockIdx.x * blockDim.x + threadIdx.x;
    const long total = (long)B_SZ * COUT * 9 * HW;
    if (idx >= total) return;
    int n = (int)(idx % HW);
    long r = idx / HW;
    int t = (int)(r % 9);  r /= 9;
    int ci = (int)(r % COUT);
    int b = (int)(r / COUT);
    int h = n / W_, w = n % W_;
    int hh = h + t / 3 - 1, ww = w + t % 3 - 1;
    float v = 0.f;
    if (hh >= 0 && hh < H_ && ww >= 0 && ww < W_)
        v = x[((long)b * COUT + ci) * HW + hh * W_ + ww];
    col[idx] = v;
}

__global__ void softmax_kernel(float* __restrict__ S, int len, float scale)
{
    float* p = S + (long)blockIdx.x * len;
    __shared__ float red[256];
    int tid = threadIdx.x;
    float mx = -1e30f;
    for (int j = tid; j < len; j += 256) mx = fmaxf(mx, p[j] * scale);
    red[tid] = mx; __syncthreads();
    for (int s = 128; s > 0; s >>= 1) {
        if (tid < s) red[tid] = fmaxf(red[tid], red[tid + s]);
        __syncthreads();
    }
    mx = red[0]; __syncthreads();
    float sum = 0.f;
    for (int j = tid; j < len; j += 256) {
        float e = expf(p[j] * scale - mx);
        p[j] = e; sum += e;
    }
    red[tid] = sum; __syncthreads();
    for (int s = 128; s > 0; s >>= 1) {
        if (tid < s) red[tid] += red[tid + s];
        __syncthreads();
    }
    float inv = 1.f / red[0];
    for (int j = tid; j < len; j += 256) p[j] *= inv;
}

__global__ void concat_kernel(const float* __restrict__ kf,
                              const float* __restrict__ x,
                              float* __restrict__ cat)
{
    long idx = (long)blockIdx.x * blockDim.x + threadIdx.x;
    const long total = (long)B_SZ * 2 * COUT * HW;
    if (idx >= total) return;
    int n = (int)(idx % HW);
    long r = idx / HW;
    int c = (int)(r % (2 * COUT));
    int b = (int)(r / (2 * COUT));
    cat[idx] = (c < COUT) ? kf[((long)b * COUT + c) * HW + n]
                          : x[((long)b * COUT + (c - COUT)) * HW + n];
}

// ---------------- host-side helpers -----------------------------------------
static const int SMB = (2 * BM + 2 * BN) * SSTR * 4;   // 72 KB

// mode: 0 = NN, 1 = TN (A transposed), 2 = NT (B transposed)
static void launch_gemm(int mode,
                        const float* A, const float* B, float* C,
                        int M, int N, int Kd, int lda, int ldb,
                        long aS, int aDiv, long bS, long cS,
                        const float* sc, const float* bi, long biS,
                        int relu, const float* gp,
                        const float* res, long rS, int Z)
{
    dim3 block(256);
    dim3 grid((N + BN - 1) / BN, (M + BM - 1) / BM, Z);
    switch (mode) {
    case 0:
        cudaFuncSetAttribute(gemm_tc<false,false>,
                             cudaFuncAttributeMaxDynamicSharedMemorySize, SMB);
        gemm_tc<false,false><<<grid, block, SMB>>>(A, B, C, M, N, Kd, lda, ldb,
            aS, aDiv, bS, cS, sc, bi, biS, relu, gp, res, rS);
        break;
    case 1:
        cudaFuncSetAttribute(gemm_tc<true,false>,
                             cudaFuncAttributeMaxDynamicSharedMemorySize, SMB);
        gemm_tc<true,false><<<grid, block, SMB>>>(A, B, C, M, N, Kd, lda, ldb,
            aS, aDiv, bS, cS, sc, bi, biS, relu, gp, res, rS);
        break;
    default:
        cudaFuncSetAttribute(gemm_tc<false,true>,
                             cudaFuncAttributeMaxDynamicSharedMemorySize, SMB);
        gemm_tc<false,true><<<grid, block, SMB>>>(A, B, C, M, N, Kd, lda, ldb,
            aS, aDiv, bS, cS, sc, bi, biS, relu, gp, res, rS);
        break;
    }
}

extern "C" void kernel_launch(void* const* d_in, const int* in_sizes, int n_in,
                              void* d_out, int out_size)
{
    const float* feats    = (const float*)d_in[0];
    const float* proj_w   = (const float*)d_in[1];
    const float* proj_b   = (const float*)d_in[2];
    const float* ts_gw    = (const float*)d_in[3];
    const float* ts_gb    = (const float*)d_in[4];
    const float* ts_w3    = (const float*)d_in[5];
    const float* ts_bn    = (const float*)d_in[6];
    const float* ssam_w1  = (const float*)d_in[7];
    const float* ssam_b1  = (const float*)d_in[8];
    const float* ssam_w2  = (const float*)d_in[9];
    const float* ssam_b2  = (const float*)d_in[10];
    const float* ssam_g   = (const float*)d_in[11];
    const float* csam_w1  = (const float*)d_in[12];
    const float* csam_b1  = (const float*)d_in[13];
    const float* csam_w2  = (const float*)d_in[14];
    const float* csam_b2  = (const float*)d_in[15];
    const float* fuse_w1  = (const float*)d_in[16];
    const float* fuse_bn1 = (const float*)d_in[17];
    const float* fuse_w2  = (const float*)d_in[18];
    const float* fuse_bn2 = (const float*)d_in[19];
    const float* fcsam_w1 = (const float*)d_in[20];
    const float* fcsam_b1 = (const float*)d_in[21];
    const float* fcsam_w2 = (const float*)d_in[22];
    const float* fcsam_b2 = (const float*)d_in[23];
    const float* fuse_w4  = (const float*)d_in[24];
    const float* fuse_bn4 = (const float*)d_in[25];
    float* out = (float*)d_out;

    float *pf, *x, *x2, *o1, *h, *aS_, *aC_, *col, *cat, *bnA, *bnB;
    cudaGetSymbolAddress((void**)&pf,  g_pf);
    cudaGetSymbolAddress((void**)&x,   g_x);
    cudaGetSymbolAddress((void**)&x2,  g_x2);
    cudaGetSymbolAddress((void**)&o1,  g_o1);
    cudaGetSymbolAddress((void**)&h,   g_h);
    cudaGetSymbolAddress((void**)&aS_, g_aS);
    cudaGetSymbolAddress((void**)&aC_, g_aC);
    cudaGetSymbolAddress((void**)&col, g_col);
    cudaGetSymbolAddress((void**)&cat, g_cat);
    cudaGetSymbolAddress((void**)&bnA, g_bnA);
    cudaGetSymbolAddress((void**)&bnB, g_bnB);

    const long SP  = (long)COUT * HW;
    const long SPH = (long)C4V * HW;
    const long SPS = (long)HW * HW;
    const long SPC = (long)COUT * COUT;
    const long SPCOL = (long)COUT * 9 * HW;
    const long SPCAT = (long)2 * COUT * HW;

    // 1. per-frame 1x1 projection
    launch_gemm(0, proj_w, feats, pf, COUT, HW, CIN, CIN, HW,
                (long)COUT * CIN, B_SZ, (long)CIN * HW, SP,
                nullptr, proj_b, COUT, 0, nullptr, nullptr, 0, K_FR * B_SZ);

    // 2. temporal shuffle + grouped 1x1 -> x
    {
        int total = B_SZ * COUT * HW;
        tshuffle_kernel<<<(total + 255) / 256, 256>>>(pf, ts_gw, ts_gb, x);
    }

    // 3. 3x3 conv + BN -> x2
    bnprep_kernel<<<1, 256>>>(ts_bn, bnA, bnB);
    {
        long total = (long)B_SZ * SPCOL;
        im2col_kernel<<<(int)((total + 255) / 256), 256>>>(x, col);
    }
    launch_gemm(0, ts_w3, col, x2, COUT, HW, COUT * 9, COUT * 9, HW,
                0, 1, SPCOL, SP, bnA, bnB, 0, 0, nullptr, nullptr, 0, B_SZ);

    // 4. spatial self-attention (input x2, output x)
    launch_gemm(1, x2, x2, aS_, HW, HW, COUT, HW, HW,
                SP, 1, SP, SPS, nullptr, nullptr, 0, 0, nullptr, nullptr, 0, B_SZ);
    softmax_kernel<<<B_SZ * HW, 256>>>(aS_, HW, 0.0625f);
    launch_gemm(2, x2, aS_, o1, COUT, HW, HW, HW, HW,
                SP, 1, SPS, SP, nullptr, nullptr, 0, 0, nullptr, nullptr, 0, B_SZ);
    launch_gemm(0, ssam_w1, o1, h, C4V, HW, COUT, COUT, HW,
                0, 1, SP, SPH, nullptr, ssam_b1, 0, 1, nullptr, nullptr, 0, B_SZ);
    launch_gemm(0, ssam_w2, h, x, COUT, HW, C4V, C4V, HW,
                0, 1, SPH, SP, nullptr, ssam_b2, 0, 0, ssam_g, x2, SP, B_SZ);

    // 5. channel self-attention (input x, output x2)
    launch_gemm(2, x, x, aC_, COUT, COUT, HW, HW, HW,
                SP, 1, SP, SPC, nullptr, nullptr, 0, 0, nullptr, nullptr, 0, B_SZ);
    softmax_kernel<<<B_SZ * COUT, 256>>>(aC_, COUT, 0.0625f);
    launch_gemm(0, aC_, x, o1, COUT, HW, COUT, COUT, HW,
                SPC, 1, SP, SP, nullptr, nullptr, 0, 0, nullptr, nullptr, 0, B_SZ);
    launch_gemm(0, csam_w1, o1, h, C4V, HW, COUT, COUT, HW,
                0, 1, SP, SPH, nullptr, csam_b1, 0, 1, nullptr, nullptr, 0, B_SZ);
    launch_gemm(0, csam_w2, h, x2, COUT, HW, C4V, C4V, HW,
                0, 1, SPH, SP, nullptr, csam_b2, 0, 0, nullptr, x, SP, B_SZ);

    // 6. fuse: concat keyframe feat (pf[K-1]) with x2
    {
        long total = (long)B_SZ * SPCAT;
        concat_kernel<<<(int)((total + 255) / 256), 256>>>(
            pf + (long)(K_FR - 1) * B_SZ * SP, x2, cat);
    }
    bnprep_kernel<<<1, 256>>>(fuse_bn1, bnA, bnB);
    launch_gemm(0, fuse_w1, cat, x, COUT, HW, 2 * COUT, 2 * COUT, HW,
                0, 1, SPCAT, SP, bnA, bnB, 0, 1, nullptr, nullptr, 0, B_SZ);

    // 7. 3x3 conv + BN + relu -> x2
    bnprep_kernel<<<1, 256>>>(fuse_bn2, bnA, bnB);
    {
        long total = (long)B_SZ * SPCOL;
        im2col_kernel<<<(int)((total + 255) / 256), 256>>>(x, col);
    }
    launch_gemm(0, fuse_w2, col, x2, COUT, HW, COUT * 9, COUT * 9, HW,
                0, 1, SPCOL, SP, bnA, bnB, 0, 1, nullptr, nullptr, 0, B_SZ);

    // 8. channel self-attention (input x2, output x)
    launch_gemm(2, x2, x2, aC_, COUT, COUT, HW, HW, HW,
                SP, 1, SP, SPC, nullptr, nullptr, 0, 0, nullptr, nullptr, 0, B_SZ);
    softmax_kernel<<<B_SZ * COUT, 256>>>(aC_, COUT, 0.0625f);
    launch_gemm(0, aC_, x2, o1, COUT, HW, COUT, COUT, HW,
                SPC, 1, SP, SP, nullptr, nullptr, 0, 0, nullptr, nullptr, 0, B_SZ);
    launch_gemm(0, fcsam_w1, o1, h, C4V, HW, COUT, COUT, HW,
                0, 1, SP, SPH, nullptr, fcsam_b1, 0, 1, nullptr, nullptr, 0, B_SZ);
    launch_gemm(0, fcsam_w2, h, x, COUT, HW, C4V, C4V, HW,
                0, 1, SPH, SP, nullptr, fcsam_b2, 0, 0, nullptr, x2, SP, B_SZ);

    // 9. final 3x3 conv + BN + relu -> d_out
    bnprep_kernel<<<1, 256>>>(fuse_bn4, bnA, bnB);
    {
        long total = (long)B_SZ * SPCOL;
        im2col_kernel<<<(int)((total + 255) / 256), 256>>>(x, col);
    }
    launch_gemm(0, fuse_w4, col, out, COUT, HW, COUT * 9, COUT * 9, HW,
                0, 1, SPCOL, SP, bnA, bnB, 0, 1, nullptr, nullptr, 0, B_SZ);
}

// round 8
// speedup vs baseline: 2.0574x; 1.7591x over previous
#include <cuda_runtime.h>
#include <cuda_bf16.h>
#include <math.h>

#define K_FR 8
#define B_SZ 8
#define CIN  512
#define COUT 256
#define H_   28
#define W_   28
#define HW   784
#define C4V  1024

// ---------------- scratch (device globals; no allocation at runtime) --------
__device__ __align__(16) float g_pf  [K_FR * B_SZ * COUT * HW];
__device__ __align__(16) float g_x   [B_SZ * COUT * HW];
__device__ __align__(16) float g_x2  [B_SZ * COUT * HW];
__device__ __align__(16) float g_o1  [B_SZ * COUT * HW];
__device__ __align__(16) float g_h   [B_SZ * C4V * HW];
__device__ __align__(16) float g_aS  [B_SZ * HW * HW];
__device__ __align__(16) float g_aC  [B_SZ * COUT * COUT];
__device__ __align__(16) float g_col [B_SZ * COUT * 9 * HW];
__device__ __align__(16) float g_cat [B_SZ * 2 * COUT * HW];
__device__ float g_bnA [COUT];
__device__ float g_bnB [COUT];

// ---------------- 3xBF16 tensor-core GEMM -----------------------------------
// a*b ~= aH*bH + aH*bL + aL*bH with bf16 hi/lo split (residual ~2^-16), fp32 acc.
// mma.m16n8k16.bf16 covers K=16 per instruction -> half the MMAs/LDS of 3xTF32.
// smem row layout (per k-tile of 16): 8 k-pairs as bf16x2 words, interleaved
//   group 4p = {hi(p), hi(p+4), lo(p), lo(p+4)}  -> fragment = one LDS.128.
// Row stride RSTR=20 uints (spreads rows over banks; uint4 stays 16B-aligned).
// TA: A stored [K,M]; else [M,K].  TB: B stored [N,K]; else [K,N].
// epilogue: v = acc*scale[m]+bias[m]; relu; v = v*gamma + resid[m,n]
// Requires Kd % 16 == 0 (all call sites: 256/512/784/1024/2304).

__device__ __forceinline__ unsigned pack2(float f0, float f1) {   // f0->low, f1->high
    unsigned r;
    asm("cvt.rn.bf16x2.f32 %0, %1, %2;" : "=r"(r) : "f"(f1), "f"(f0));
    return r;
}
__device__ __forceinline__ void split2(float f0, float f1, unsigned& hi, unsigned& lo) {
    hi = pack2(f0, f1);
    float h0 = __uint_as_float(hi << 16);
    float h1 = __uint_as_float(hi & 0xffff0000u);
    lo = pack2(f0 - h0, f1 - h1);
}
__device__ __forceinline__ void mma_bf16(float4& d, const unsigned a[4], const unsigned b[2]) {
    asm volatile(
        "mma.sync.aligned.m16n8k16.row.col.f32.bf16.bf16.f32 "
        "{%0,%1,%2,%3}, {%4,%5,%6,%7}, {%8,%9}, {%0,%1,%2,%3};"
        : "+f"(d.x), "+f"(d.y), "+f"(d.z), "+f"(d.w)
        : "r"(a[0]), "r"(a[1]), "r"(a[2]), "r"(a[3]), "r"(b[0]), "r"(b[1]));
}

#define RSTR 20   // smem row stride in uints
#define BN   128

__device__ __forceinline__ int posH(int p) { return 4 * (p & 3) + (p >> 2); }

template <int TBM, bool TA, bool TB, int MAXB>
__global__ void __launch_bounds__(256, MAXB) gemm_bf(
    const float* __restrict__ A, const float* __restrict__ Bm, float* __restrict__ C,
    int M, int N, int Kd, int lda, int ldb,
    long aS, int aDiv, long bS, long cS,
    const float* __restrict__ scaleC, const float* __restrict__ biasC, long biS,
    int relu, const float* __restrict__ gammaPtr,
    const float* __restrict__ resid, long rS)
{
    extern __shared__ unsigned sm[];
    unsigned* As = sm;                       // [2][TBM][RSTR]
    unsigned* Bs = sm + 2 * TBM * RSTR;      // [2][BN ][RSTR]

    const int z = blockIdx.z;
    A  += (long)(z / aDiv) * aS;
    Bm += (long)z * bS;
    C  += (long)z * cS;
    if (biasC) biasC += (long)(z / aDiv) * biS;
    if (resid) resid += (long)z * rS;

    const int tid  = threadIdx.x;
    const int lane = tid & 31, warp = tid >> 5;
    constexpr int MI = TBM / 32;            // 2 or 4
    constexpr int NJ = 4;
    constexpr int UA = TBM / 32;            // A pairs per thread
    constexpr int UB = 4;                   // B pairs per thread
    constexpr int LBM = (TBM == 128) ? 7 : 6;
    const int wm = (warp >> 2) * (TBM / 2);
    const int wn = (warp & 3) * 32;
    const int m0 = blockIdx.y * TBM, n0 = blockIdx.x * BN;

    float4 acc[MI][NJ];
    #pragma unroll
    for (int i = 0; i < MI; ++i)
        #pragma unroll
        for (int j = 0; j < NJ; ++j)
            acc[i][j] = make_float4(0.f, 0.f, 0.f, 0.f);

    float2 va[UA], vb[UB];

    auto loadA = [&](int k0) {
        if (!TA) {   // A [M,K]: 8 threads per row, float2 (k-pair) each
            #pragma unroll
            for (int t = 0; t < UA; ++t) {
                int i = tid + t * 256;
                int p = i & 7, m = i >> 3;
                int gm = m0 + m;
                va[t] = (gm < M) ? *(const float2*)&A[(long)gm * lda + k0 + 2 * p]
                                 : make_float2(0.f, 0.f);
            }
        } else {     // A [K,M]: coalesced across m, two strided rows per pair
            int m = tid & (TBM - 1), psel = tid >> LBM;
            int gm = m0 + m;
            #pragma unroll
            for (int t = 0; t < UA; ++t) {
                int p = psel * UA + t;
                float f0 = 0.f, f1 = 0.f;
                if (gm < M) {
                    f0 = A[(long)(k0 + 2 * p) * lda + gm];
                    f1 = A[(long)(k0 + 2 * p + 1) * lda + gm];
                }
                va[t] = make_float2(f0, f1);
            }
        }
    };
    auto loadB = [&](int k0) {
        if (TB) {    // B [N,K]: 8 threads per row, float2 each
            #pragma unroll
            for (int t = 0; t < UB; ++t) {
                int i = tid + t * 256;
                int p = i & 7, n = i >> 3;
                int gn = n0 + n;
                vb[t] = (gn < N) ? *(const float2*)&Bm[(long)gn * ldb + k0 + 2 * p]
                                 : make_float2(0.f, 0.f);
            }
        } else {     // B [K,N]: coalesced across n, two strided rows per pair
            int n = tid & 127, psel = tid >> 7;
            int gn = n0 + n;
            #pragma unroll
            for (int t = 0; t < UB; ++t) {
                int p = psel * UB + t;
                float f0 = 0.f, f1 = 0.f;
                if (gn < N) {
                    f0 = Bm[(long)(k0 + 2 * p) * ldb + gn];
                    f1 = Bm[(long)(k0 + 2 * p + 1) * ldb + gn];
                }
                vb[t] = make_float2(f0, f1);
            }
        }
    };
    auto storeA = [&](int buf) {
        if (!TA) {
            #pragma unroll
            for (int t = 0; t < UA; ++t) {
                int i = tid + t * 256;
                int p = i & 7, m = i >> 3;
                unsigned hi, lo;
                split2(va[t].x, va[t].y, hi, lo);
                unsigned* base = &As[(long)(buf * TBM + m) * RSTR];
                int ph = posH(p);
                base[ph]     = hi;
                base[ph + 2] = lo;
            }
        } else {
            int m = tid & (TBM - 1), psel = tid >> LBM;
            #pragma unroll
            for (int t = 0; t < UA; ++t) {
                int p = psel * UA + t;
                unsigned hi, lo;
                split2(va[t].x, va[t].y, hi, lo);
                unsigned* base = &As[(long)(buf * TBM + m) * RSTR];
                int ph = posH(p);
                base[ph]     = hi;
                base[ph + 2] = lo;
            }
        }
    };
    auto storeB = [&](int buf) {
        if (TB) {
            #pragma unroll
            for (int t = 0; t < UB; ++t) {
                int i = tid + t * 256;
                int p = i & 7, n = i >> 3;
                unsigned hi, lo;
                split2(vb[t].x, vb[t].y, hi, lo);
                unsigned* base = &Bs[(long)(buf * BN + n) * RSTR];
                int ph = posH(p);
                base[ph]     = hi;
                base[ph + 2] = lo;
            }
        } else {
            int n = tid & 127, psel = tid >> 7;
            #pragma unroll
            for (int t = 0; t < UB; ++t) {
                int p = psel * UB + t;
                unsigned hi, lo;
                split2(vb[t].x, vb[t].y, hi, lo);
                unsigned* base = &Bs[(long)(buf * BN + n) * RSTR];
                int ph = posH(p);
                base[ph]     = hi;
                base[ph + 2] = lo;
            }
        }
    };
    auto compute = [&](int buf) {
        uint4 a0[MI], a1[MI], bv[NJ];
        #pragma unroll
        for (int i = 0; i < MI; ++i) {
            int r = wm + i * 16 + (lane >> 2);
            a0[i] = *(const uint4*)&As[(long)(buf * TBM + r) * RSTR + ((lane & 3) << 2)];
            a1[i] = *(const uint4*)&As[(long)(buf * TBM + r + 8) * RSTR + ((lane & 3) << 2)];
        }
        #pragma unroll
        for (int j = 0; j < NJ; ++j) {
            int c = wn + j * 8 + (lane >> 2);
            bv[j] = *(const uint4*)&Bs[(long)(buf * BN + c) * RSTR + ((lane & 3) << 2)];
        }
        unsigned aH[MI][4], aL[MI][4], bH[NJ][2], bL[NJ][2];
        #pragma unroll
        for (int i = 0; i < MI; ++i) {
            aH[i][0] = a0[i].x; aH[i][1] = a1[i].x; aH[i][2] = a0[i].y; aH[i][3] = a1[i].y;
            aL[i][0] = a0[i].z; aL[i][1] = a1[i].z; aL[i][2] = a0[i].w; aL[i][3] = a1[i].w;
        }
        #pragma unroll
        for (int j = 0; j < NJ; ++j) {
            bH[j][0] = bv[j].x; bH[j][1] = bv[j].y;
            bL[j][0] = bv[j].z; bL[j][1] = bv[j].w;
        }
        #pragma unroll
        for (int j = 0; j < NJ; ++j)
            #pragma unroll
            for (int i = 0; i < MI; ++i)
                mma_bf16(acc[i][j], aH[i], bH[j]);   // hi*hi
        #pragma unroll
        for (int j = 0; j < NJ; ++j)
            #pragma unroll
            for (int i = 0; i < MI; ++i)
                mma_bf16(acc[i][j], aH[i], bL[j]);   // hi*lo
        #pragma unroll
        for (int j = 0; j < NJ; ++j)
            #pragma unroll
            for (int i = 0; i < MI; ++i)
                mma_bf16(acc[i][j], aL[i], bH[j]);   // lo*hi
    };

    int buf = 0;
    loadA(0); loadB(0);
    storeA(0); storeB(0);
    __syncthreads();

    for (int k0 = 0; k0 < Kd; k0 += 16) {
        bool more = (k0 + 16) < Kd;
        if (more) { loadA(k0 + 16); loadB(k0 + 16); }
        compute(buf);
        if (more) {
            storeA(buf ^ 1); storeB(buf ^ 1);
            __syncthreads();
            buf ^= 1;
        }
    }

    const float gmv = gammaPtr ? *gammaPtr : 1.f;
    #pragma unroll
    for (int i = 0; i < MI; ++i) {
        int r0 = m0 + wm + i * 16 + (lane >> 2);
        int r1 = r0 + 8;
        float sc0 = 1.f, bi0 = 0.f, sc1 = 1.f, bi1 = 0.f;
        if (scaleC) { if (r0 < M) sc0 = scaleC[r0]; if (r1 < M) sc1 = scaleC[r1]; }
        if (biasC)  { if (r0 < M) bi0 = biasC[r0];  if (r1 < M) bi1 = biasC[r1]; }
        #pragma unroll
        for (int j = 0; j < NJ; ++j) {
            int c = n0 + wn + j * 8 + ((lane & 3) << 1);
            float4 v = acc[i][j];
            if (r0 < M) {
                float x0 = v.x * sc0 + bi0, x1 = v.y * sc0 + bi0;
                if (relu) { x0 = fmaxf(x0, 0.f); x1 = fmaxf(x1, 0.f); }
                if (resid) {
                    if (c < N)     x0 = x0 * gmv + resid[(long)r0 * N + c];
                    if (c + 1 < N) x1 = x1 * gmv + resid[(long)r0 * N + c + 1];
                }
                if (c < N)     C[(long)r0 * N + c]     = x0;
                if (c + 1 < N) C[(long)r0 * N + c + 1] = x1;
            }
            if (r1 < M) {
                float y0 = v.z * sc1 + bi1, y1 = v.w * sc1 + bi1;
                if (relu) { y0 = fmaxf(y0, 0.f); y1 = fmaxf(y1, 0.f); }
                if (resid) {
                    if (c < N)     y0 = y0 * gmv + resid[(long)r1 * N + c];
                    if (c + 1 < N) y1 = y1 * gmv + resid[(long)r1 * N + c + 1];
                }
                if (c < N)     C[(long)r1 * N + c]     = y0;
                if (c + 1 < N) C[(long)r1 * N + c + 1] = y1;
            }
        }
    }
}

// ---------------- pointwise kernels -----------------------------------------
__global__ void tshuffle_kernel(const float* __restrict__ pf,
                                const float* __restrict__ gw,
                                const float* __restrict__ gb,
                                float* __restrict__ out)
{
    int idx = blockIdx.x * blockDim.x + threadIdx.x;
    if (idx >= B_SZ * COUT * HW) return;
    int c = (idx / HW) % COUT;
    float s = gb[c];
    #pragma unroll
    for (int k = 0; k < K_FR; ++k)
        s = fmaf(pf[(long)k * (B_SZ * COUT * HW) + idx], gw[c * K_FR + k], s);
    out[idx] = s;
}

__global__ void bnprep_kernel(const float* __restrict__ p,
                              float* __restrict__ a, float* __restrict__ b)
{
    int c = blockIdx.x * blockDim.x + threadIdx.x;
    if (c >= COUT) return;
    float g = p[c], be = p[COUT + c], m = p[2 * COUT + c], v = p[3 * COUT + c];
    float s = g * rsqrtf(v + 1e-5f);
    a[c] = s;
    b[c] = be - m * s;
}

__global__ void im2col_kernel(const float* __restrict__ x, float* __restrict__ col)
{
    long idx = (long)blockIdx.x * blockDim.x + threadIdx.x;
    const long total = (long)B_SZ * COUT * 9 * HW;
    if (idx >= total) return;
    int n = (int)(idx % HW);
    long r = idx / HW;
    int t = (int)(r % 9);  r /= 9;
    int ci = (int)(r % COUT);
    int b = (int)(r / COUT);
    int h = n / W_, w = n % W_;
    int hh = h + t / 3 - 1, ww = w + t % 3 - 1;
    float v = 0.f;
    if (hh >= 0 && hh < H_ && ww >= 0 && ww < W_)
        v = x[((long)b * COUT + ci) * HW + hh * W_ + ww];
    col[idx] = v;
}

__global__ void softmax_kernel(float* __restrict__ S, int len, float scale)
{
    float* p = S + (long)blockIdx.x * len;
    __shared__ float red[256];
    int tid = threadIdx.x;
    float mx = -1e30f;
    for (int j = tid; j < len; j += 256) mx = fmaxf(mx, p[j] * scale);
    red[tid] = mx; __syncthreads();
    for (int s = 128; s > 0; s >>= 1) {
        if (tid < s) red[tid] = fmaxf(red[tid], red[tid + s]);
        __syncthreads();
    }
    mx = red[0]; __syncthreads();
    float sum = 0.f;
    for (int j = tid; j < len; j += 256) {
        float e = expf(p[j] * scale - mx);
        p[j] = e; sum += e;
    }
    red[tid] = sum; __syncthreads();
    for (int s = 128; s > 0; s >>= 1) {
        if (tid < s) red[tid] += red[tid + s];
        __syncthreads();
    }
    float inv = 1.f / red[0];
    for (int j = tid; j < len; j += 256) p[j] *= inv;
}

__global__ void concat_kernel(const float* __restrict__ kf,
                              const float* __restrict__ x,
                              float* __restrict__ cat)
{
    long idx = (long)blockIdx.x * blockDim.x + threadIdx.x;
    const long total = (long)B_SZ * 2 * COUT * HW;
    if (idx >= total) return;
    int n = (int)(idx % HW);
    long r = idx / HW;
    int c = (int)(r % (2 * COUT));
    int b = (int)(r / (2 * COUT));
    cat[idx] = (c < COUT) ? kf[((long)b * COUT + c) * HW + n]
                          : x[((long)b * COUT + (c - COUT)) * HW + n];
}

// ---------------- host-side helpers -----------------------------------------
static const int SMB_BIG   = (2 * 128 + 2 * 128) * RSTR * 4;   // 40960
static const int SMB_SMALL = (2 * 64 + 2 * 128) * RSTR * 4;    // 30720

// big: 128x128 tile (1 CTA); small: 64x128 tile (2 CTAs)
// mode: 0 = NN, 1 = TN (A transposed), 2 = NT (B transposed)
static void launch_gemm(int big, int mode,
                        const float* A, const float* B, float* C,
                        int M, int N, int Kd, int lda, int ldb,
                        long aS, int aDiv, long bS, long cS,
                        const float* sc, const float* bi, long biS,
                        int relu, const float* gp,
                        const float* res, long rS, int Z)
{
    dim3 block(256);
    if (big) {
        dim3 grid((N + 127) / 128, (M + 127) / 128, Z);
        if (mode == 0) {
            cudaFuncSetAttribute(gemm_bf<128,false,false,1>,
                                 cudaFuncAttributeMaxDynamicSharedMemorySize, SMB_BIG);
            gemm_bf<128,false,false,1><<<grid, block, SMB_BIG>>>(A, B, C, M, N, Kd, lda, ldb,
                aS, aDiv, bS, cS, sc, bi, biS, relu, gp, res, rS);
        } else {  // mode 1
            cudaFuncSetAttribute(gemm_bf<128,true,false,1>,
                                 cudaFuncAttributeMaxDynamicSharedMemorySize, SMB_BIG);
            gemm_bf<128,true,false,1><<<grid, block, SMB_BIG>>>(A, B, C, M, N, Kd, lda, ldb,
                aS, aDiv, bS, cS, sc, bi, biS, relu, gp, res, rS);
        }
    } else {
        dim3 grid((N + 127) / 128, (M + 63) / 64, Z);
        if (mode == 0) {
            cudaFuncSetAttribute(gemm_bf<64,false,false,2>,
                                 cudaFuncAttributeMaxDynamicSharedMemorySize, SMB_SMALL);
            gemm_bf<64,false,false,2><<<grid, block, SMB_SMALL>>>(A, B, C, M, N, Kd, lda, ldb,
                aS, aDiv, bS, cS, sc, bi, biS, relu, gp, res, rS);
        } else {  // mode 2
            cudaFuncSetAttribute(gemm_bf<64,false,true,2>,
                                 cudaFuncAttributeMaxDynamicSharedMemorySize, SMB_SMALL);
            gemm_bf<64,false,true,2><<<grid, block, SMB_SMALL>>>(A, B, C, M, N, Kd, lda, ldb,
                aS, aDiv, bS, cS, sc, bi, biS, relu, gp, res, rS);
        }
    }
}

extern "C" void kernel_launch(void* const* d_in, const int* in_sizes, int n_in,
                              void* d_out, int out_size)
{
    const float* feats    = (const float*)d_in[0];
    const float* proj_w   = (const float*)d_in[1];
    const float* proj_b   = (const float*)d_in[2];
    const float* ts_gw    = (const float*)d_in[3];
    const float* ts_gb    = (const float*)d_in[4];
    const float* ts_w3    = (const float*)d_in[5];
    const float* ts_bn    = (const float*)d_in[6];
    const float* ssam_w1  = (const float*)d_in[7];
    const float* ssam_b1  = (const float*)d_in[8];
    const float* ssam_w2  = (const float*)d_in[9];
    const float* ssam_b2  = (const float*)d_in[10];
    const float* ssam_g   = (const float*)d_in[11];
    const float* csam_w1  = (const float*)d_in[12];
    const float* csam_b1  = (const float*)d_in[13];
    const float* csam_w2  = (const float*)d_in[14];
    const float* csam_b2  = (const float*)d_in[15];
    const float* fuse_w1  = (const float*)d_in[16];
    const float* fuse_bn1 = (const float*)d_in[17];
    const float* fuse_w2  = (const float*)d_in[18];
    const float* fuse_bn2 = (const float*)d_in[19];
    const float* fcsam_w1 = (const float*)d_in[20];
    const float* fcsam_b1 = (const float*)d_in[21];
    const float* fcsam_w2 = (const float*)d_in[22];
    const float* fcsam_b2 = (const float*)d_in[23];
    const float* fuse_w4  = (const float*)d_in[24];
    const float* fuse_bn4 = (const float*)d_in[25];
    float* out = (float*)d_out;

    float *pf, *x, *x2, *o1, *h, *aS_, *aC_, *col, *cat, *bnA, *bnB;
    cudaGetSymbolAddress((void**)&pf,  g_pf);
    cudaGetSymbolAddress((void**)&x,   g_x);
    cudaGetSymbolAddress((void**)&x2,  g_x2);
    cudaGetSymbolAddress((void**)&o1,  g_o1);
    cudaGetSymbolAddress((void**)&h,   g_h);
    cudaGetSymbolAddress((void**)&aS_, g_aS);
    cudaGetSymbolAddress((void**)&aC_, g_aC);
    cudaGetSymbolAddress((void**)&col, g_col);
    cudaGetSymbolAddress((void**)&cat, g_cat);
    cudaGetSymbolAddress((void**)&bnA, g_bnA);
    cudaGetSymbolAddress((void**)&bnB, g_bnB);

    const long SP  = (long)COUT * HW;
    const long SPH = (long)C4V * HW;
    const long SPS = (long)HW * HW;
    const long SPC = (long)COUT * COUT;
    const long SPCOL = (long)COUT * 9 * HW;
    const long SPCAT = (long)2 * COUT * HW;

    // 1. per-frame 1x1 projection
    launch_gemm(1, 0, proj_w, feats, pf, COUT, HW, CIN, CIN, HW,
                (long)COUT * CIN, B_SZ, (long)CIN * HW, SP,
                nullptr, proj_b, COUT, 0, nullptr, nullptr, 0, K_FR * B_SZ);

    // 2. temporal shuffle + grouped 1x1 -> x
    {
        int total = B_SZ * COUT * HW;
        tshuffle_kernel<<<(total + 255) / 256, 256>>>(pf, ts_gw, ts_gb, x);
    }

    // 3. 3x3 conv + BN -> x2
    bnprep_kernel<<<1, 256>>>(ts_bn, bnA, bnB);
    {
        long total = (long)B_SZ * SPCOL;
        im2col_kernel<<<(int)((total + 255) / 256), 256>>>(x, col);
    }
    launch_gemm(0, 0, ts_w3, col, x2, COUT, HW, COUT * 9, COUT * 9, HW,
                0, 1, SPCOL, SP, bnA, bnB, 0, 0, nullptr, nullptr, 0, B_SZ);

    // 4. spatial self-attention (input x2, output x)
    launch_gemm(1, 1, x2, x2, aS_, HW, HW, COUT, HW, HW,
                SP, 1, SP, SPS, nullptr, nullptr, 0, 0, nullptr, nullptr, 0, B_SZ);
    softmax_kernel<<<B_SZ * HW, 256>>>(aS_, HW, 0.0625f);
    launch_gemm(0, 2, x2, aS_, o1, COUT, HW, HW, HW, HW,
                SP, 1, SPS, SP, nullptr, nullptr, 0, 0, nullptr, nullptr, 0, B_SZ);
    launch_gemm(1, 0, ssam_w1, o1, h, C4V, HW, COUT, COUT, HW,
                0, 1, SP, SPH, nullptr, ssam_b1, 0, 1, nullptr, nullptr, 0, B_SZ);
    launch_gemm(0, 0, ssam_w2, h, x, COUT, HW, C4V, C4V, HW,
                0, 1, SPH, SP, nullptr, ssam_b2, 0, 0, ssam_g, x2, SP, B_SZ);

    // 5. channel self-attention (input x, output x2)
    launch_gemm(0, 2, x, x, aC_, COUT, COUT, HW, HW, HW,
                SP, 1, SP, SPC, nullptr, nullptr, 0, 0, nullptr, nullptr, 0, B_SZ);
    softmax_kernel<<<B_SZ * COUT, 256>>>(aC_, COUT, 0.0625f);
    launch_gemm(0, 0, aC_, x, o1, COUT, HW, COUT, COUT, HW,
                SPC, 1, SP, SP, nullptr, nullptr, 0, 0, nullptr, nullptr, 0, B_SZ);
    launch_gemm(1, 0, csam_w1, o1, h, C4V, HW, COUT, COUT, HW,
                0, 1, SP, SPH, nullptr, csam_b1, 0, 1, nullptr, nullptr, 0, B_SZ);
    launch_gemm(0, 0, csam_w2, h, x2, COUT, HW, C4V, C4V, HW,
                0, 1, SPH, SP, nullptr, csam_b2, 0, 0, nullptr, x, SP, B_SZ);

    // 6. fuse: concat keyframe feat (pf[K-1]) with x2
    {
        long total = (long)B_SZ * SPCAT;
        concat_kernel<<<(int)((total + 255) / 256), 256>>>(
            pf + (long)(K_FR - 1) * B_SZ * SP, x2, cat);
    }
    bnprep_kernel<<<1, 256>>>(fuse_bn1, bnA, bnB);
    launch_gemm(0, 0, fuse_w1, cat, x, COUT, HW, 2 * COUT, 2 * COUT, HW,
                0, 1, SPCAT, SP, bnA, bnB, 0, 1, nullptr, nullptr, 0, B_SZ);

    // 7. 3x3 conv + BN + relu -> x2
    bnprep_kernel<<<1, 256>>>(fuse_bn2, bnA, bnB);
    {
        long total = (long)B_SZ * SPCOL;
        im2col_kernel<<<(int)((total + 255) / 256), 256>>>(x, col);
    }
    launch_gemm(0, 0, fuse_w2, col, x2, COUT, HW, COUT * 9, COUT * 9, HW,
                0, 1, SPCOL, SP, bnA, bnB, 0, 1, nullptr, nullptr, 0, B_SZ);

    // 8. channel self-attention (input x2, output x)
    launch_gemm(0, 2, x2, x2, aC_, COUT, COUT, HW, HW, HW,
                SP, 1, SP, SPC, nullptr, nullptr, 0, 0, nullptr, nullptr, 0, B_SZ);
    softmax_kernel<<<B_SZ * COUT, 256>>>(aC_, COUT, 0.0625f);
    launch_gemm(0, 0, aC_, x2, o1, COUT, HW, COUT, COUT, HW,
                SPC, 1, SP, SP, nullptr, nullptr, 0, 0, nullptr, nullptr, 0, B_SZ);
    launch_gemm(1, 0, fcsam_w1, o1, h, C4V, HW, COUT, COUT, HW,
                0, 1, SP, SPH, nullptr, fcsam_b1, 0, 1, nullptr, nullptr, 0, B_SZ);
    launch_gemm(0, 0, fcsam_w2, h, x, COUT, HW, C4V, C4V, HW,
                0, 1, SPH, SP, nullptr, fcsam_b2, 0, 0, nullptr, x2, SP, B_SZ);

    // 9. final 3x3 conv + BN + relu -> d_out
    bnprep_kernel<<<1, 256>>>(fuse_bn4, bnA, bnB);
    {
        long total = (long)B_SZ * SPCOL;
        im2col_kernel<<<(int)((total + 255) / 256), 256>>>(x, col);
    }
    launch_gemm(0, 0, fuse_w4, col, out, COUT, HW, COUT * 9, COUT * 9, HW,
                0, 1, SPCOL, SP, bnA, bnB, 0, 1, nullptr, nullptr, 0, B_SZ);
}